// round 1
// baseline (speedup 1.0000x reference)
#include <cuda_runtime.h>

// Problem constants
#define NB    2
#define NT    5
#define NGRID 1024            // 32*32 spatial points
#define NQ    5120            // NT * NGRID
#define NOPS  8               // NB * (NT-1) operators

// Stencil coefficient table: [op][offset(dy+1)*3+(dx+1)][point]
// ~1.18 MB device-global scratch (allocation-free rule).
__device__ float g_CO[NOPS * 9 * NGRID];

__device__ __forceinline__ float sp10(float x) {
    // softplus(10x)/10 computed as logaddexp(z,0)/10 (matches jax.nn.softplus)
    float z = 10.f * x;
    return (fmaxf(z, 0.f) + log1pf(expf(-fabsf(z)))) * 0.1f;
}

// ---------------------------------------------------------------------------
// Kernel 1: decode params -> 9-point stencil coefficients of A per (b, op, p)
// ---------------------------------------------------------------------------
__global__ void decode_kernel(const float* __restrict__ params) {
    int tid = blockIdx.x * blockDim.x + threadIdx.x;   // 0..8191
    if (tid >= NOPS * NGRID) return;
    int p  = tid & (NGRID - 1);
    int op = tid >> 10;          // 0..7
    int b  = op >> 2;
    int i  = op & 3;             // operator index 0..3
    int t  = i + 1;              // time slice 1..4

    // kappa / m use the "raw reshape" mixing: flat = p*5 + t over a (5,32,32) block
    int flat = p * 5 + t;
    int tor  = flat >> 10;       // flat / 1024
    int rem  = flat & 1023;      // -> (y, x) inside 32x32

    const float* Pb = params + b * 35 * NGRID;
    float kap = sp10(Pb[(0  + tor) * NGRID + rem]);
    float m1  =      Pb[(5  + tor) * NGRID + rem];
    float m2  =      Pb[(10 + tor) * NGRID + rem];

    // gamma / vx / vy: the transpose+reshape path is consistent -> direct (t, p)
    float gam = sp10(Pb[(15 + t) * NGRID + p]);
    float vx  =      Pb[(20 + t) * NGRID + p];
    float vy  =      Pb[(25 + t) * NGRID + p];

    float H11 = gam + vx * vx;
    float H22 = gam + vy * vy;
    float H12 = vx * vy;         // 0.5*(H01+H10) = vx*vy

    int y = p >> 5, x = p & 31;

    float co[9];
    // offset index o = (dy+1)*3 + (dx+1)
    co[4] = kap * kap + 2.f * H11 + 2.f * H22;                         // ( 0, 0)
    co[5] = (x + 1 < 32)            ? (-H11 + 0.5f * m1) : 0.f;        // ( 1, 0)
    co[3] = (x - 1 >= 0)            ? (-H11 - 0.5f * m1) : 0.f;        // (-1, 0)
    co[7] = (y + 1 < 32)            ? (-H22 + 0.5f * m2) : 0.f;        // ( 0, 1)
    co[1] = (y - 1 >= 0)            ? (-H22 - 0.5f * m2) : 0.f;        // ( 0,-1)
    co[8] = (x + 1 < 32 && y + 1 < 32) ? (-0.5f * H12) : 0.f;          // ( 1, 1)
    co[0] = (x - 1 >= 0 && y - 1 >= 0) ? (-0.5f * H12) : 0.f;          // (-1,-1)
    co[2] = (x + 1 < 32 && y - 1 >= 0) ? ( 0.5f * H12) : 0.f;          // ( 1,-1)
    co[6] = (x - 1 >= 0 && y + 1 < 32) ? ( 0.5f * H12) : 0.f;          // (-1, 1)

#pragma unroll
    for (int o = 0; o < 9; ++o)
        g_CO[(op * 9 + o) * NGRID + p] = co[o];
}

// ---------------------------------------------------------------------------
// Kernel 2: write the full Q. One float4 store per thread.
// ---------------------------------------------------------------------------
__global__ void __launch_bounds__(256) build_q_kernel(float4* __restrict__ out) {
    int g  = blockIdx.x * blockDim.x + threadIdx.x;    // 0 .. 13107199
    int c4 = g % 1280;                                  // float4 column
    int t1 = g / 1280;
    int R  = t1 % NQ;
    int b  = t1 / NQ;

    int C0 = c4 << 2;
    int ti = R  >> 10, r  = R  & 1023;
    int tj = C0 >> 10, cb = C0 & 1023;
    int d  = ti - tj;
    int ad = d < 0 ? -d : d;

    float4 o4 = make_float4(0.f, 0.f, 0.f, 0.f);

    if (ad <= 1) {
        int ry = r >> 5, rx = r & 31;
        float v[4];
#pragma unroll
        for (int j = 0; j < 4; ++j) {
            int c  = cb + j;
            int cy = c >> 5, cx = c & 31;
            int dy = cy - ry, dx = cx - rx;
            float val = 0.f;

            if (ad == 1) {
                // off-diagonal block: -0.5*(invM[i] + invM[i]^T), i = min(ti,tj)
                if (dy >= -1 && dy <= 1 && dx >= -1 && dx <= 1) {
                    int i  = ti < tj ? ti : tj;
                    int op = b * 4 + i;
                    float a  = g_CO[(op * 9 + (dy + 1) * 3 + (dx + 1)) * NGRID + r];
                    float bb = g_CO[(op * 9 + (1 - dy) * 3 + (1 - dx)) * NGRID + c];
                    float dg = (r == c) ? 2.f : 0.f;
                    val = -0.5f * (a + bb + dg);
                }
            } else {
                // diagonal block
                if (dy >= -2 && dy <= 2 && dx >= -2 && dx <= 2) {
                    if (ti == 0) {
                        // B0^T B0 + I  (+0.05 I), already symmetric
                        int op = b * 4;
                        float acc = 0.f;
#pragma unroll
                        for (int dky = -1; dky <= 1; ++dky)
#pragma unroll
                        for (int dkx = -1; dkx <= 1; ++dkx) {
                            int ky = ry + dky, kx = rx + dkx;
                            int ody = cy - ky, odx = cx - kx;
                            if (ky >= 0 && ky < 32 && kx >= 0 && kx < 32 &&
                                ody >= -1 && ody <= 1 && odx >= -1 && odx <= 1) {
                                int k = (ky << 5) + kx;
                                float a  = g_CO[(op * 9 + (1 - dky) * 3 + (1 - dkx)) * NGRID + k]; // A[k][r]
                                float bb = g_CO[(op * 9 + (ody + 1) * 3 + (odx + 1)) * NGRID + k]; // A[k][c]
                                acc = fmaf(a, bb, acc);
                            }
                        }
                        val = acc + ((r == c) ? 1.05f : 0.f);
                    } else {
                        // 0.5*(M2 + M2^T) (+I for ti=1..3) (+0.05 I)
                        int op = b * 4 + (ti - 1);
                        float acc1 = 0.f, acc2 = 0.f;
#pragma unroll
                        for (int dky = -1; dky <= 1; ++dky)
#pragma unroll
                        for (int dkx = -1; dkx <= 1; ++dkx) {
                            int ky = ry + dky, kx = rx + dkx;
                            int ody = cy - ky, odx = cx - kx;
                            if (ky >= 0 && ky < 32 && kx >= 0 && kx < 32 &&
                                ody >= -1 && ody <= 1 && odx >= -1 && odx <= 1) {
                                int k = (ky << 5) + kx;
                                float dkr = (k == r) ? 1.f : 0.f;
                                float dkc = (k == c) ? 1.f : 0.f;
                                float iM_rk = g_CO[(op * 9 + (dky + 1) * 3 + (dkx + 1)) * NGRID + r] + dkr;
                                float iM_kr = g_CO[(op * 9 + (1 - dky) * 3 + (1 - dkx)) * NGRID + k] + dkr;
                                float iM_kc = g_CO[(op * 9 + (ody + 1) * 3 + (odx + 1)) * NGRID + k] + dkc;
                                float iM_ck = g_CO[(op * 9 + (1 - ody) * 3 + (1 - odx)) * NGRID + c] + dkc;
                                acc1 = fmaf(iM_rk, iM_kc, acc1);
                                acc2 = fmaf(iM_ck, iM_kr, acc2);
                            }
                        }
                        val = 0.5f * (acc1 + acc2);
                        if (r == c) val += (ti == 4) ? 0.05f : 1.05f;
                    }
                }
            }
            v[j] = val;
        }
        o4 = make_float4(v[0], v[1], v[2], v[3]);
    }
    out[g] = o4;
}

extern "C" void kernel_launch(void* const* d_in, const int* in_sizes, int n_in,
                              void* d_out, int out_size) {
    const float* params = (const float*)d_in[0];
    float4* out = (float4*)d_out;

    decode_kernel<<<32, 256>>>(params);

    // total float4 elements: 2 * 5120 * 1280 = 13,107,200 -> 51200 blocks of 256
    build_q_kernel<<<51200, 256>>>(out);
}

// round 2
// speedup vs baseline: 1.9943x; 1.9943x over previous
#include <cuda_runtime.h>

// Problem constants
#define NB    2
#define NT    5
#define NGRID 1024            // 32*32 spatial points
#define NQ    5120            // NT * NGRID
#define NOPS  8               // NB * (NT-1) operators

// Stencil coefficient table: [op][offset(dy+1)*3+(dx+1)][point]
__device__ float g_CO[NOPS * 9 * NGRID];
// Diagonal-block band values: [b*5+ti][row][25 offsets, padded to 32]
__device__ float g_diag[NB * NT * NGRID * 32];
// Off-diagonal-block band values: [b*4+i][row][9 offsets, padded to 16]
__device__ float g_off[NB * 4 * NGRID * 16];

__device__ __forceinline__ float sp10(float x) {
    float z = 10.f * x;
    return (fmaxf(z, 0.f) + log1pf(expf(-fabsf(z)))) * 0.1f;
}

// ---------------------------------------------------------------------------
// Kernel 1: decode params -> 9-point stencil coefficients of A per (b, op, p)
// ---------------------------------------------------------------------------
__global__ void decode_kernel(const float* __restrict__ params) {
    int tid = blockIdx.x * blockDim.x + threadIdx.x;   // 0..8191
    if (tid >= NOPS * NGRID) return;
    int p  = tid & (NGRID - 1);
    int op = tid >> 10;          // 0..7
    int b  = op >> 2;
    int i  = op & 3;             // operator index 0..3
    int t  = i + 1;              // time slice 1..4

    // kappa / m use the "raw reshape" mixing: flat = p*5 + t over a (5,32,32) block
    int flat = p * 5 + t;
    int tor  = flat >> 10;
    int rem  = flat & 1023;

    const float* Pb = params + b * 35 * NGRID;
    float kap = sp10(Pb[(0  + tor) * NGRID + rem]);
    float m1  =      Pb[(5  + tor) * NGRID + rem];
    float m2  =      Pb[(10 + tor) * NGRID + rem];

    float gam = sp10(Pb[(15 + t) * NGRID + p]);
    float vx  =      Pb[(20 + t) * NGRID + p];
    float vy  =      Pb[(25 + t) * NGRID + p];

    float H11 = gam + vx * vx;
    float H22 = gam + vy * vy;
    float H12 = vx * vy;

    int y = p >> 5, x = p & 31;

    float co[9];
    co[4] = kap * kap + 2.f * H11 + 2.f * H22;
    co[5] = (x + 1 < 32)            ? (-H11 + 0.5f * m1) : 0.f;
    co[3] = (x - 1 >= 0)            ? (-H11 - 0.5f * m1) : 0.f;
    co[7] = (y + 1 < 32)            ? (-H22 + 0.5f * m2) : 0.f;
    co[1] = (y - 1 >= 0)            ? (-H22 - 0.5f * m2) : 0.f;
    co[8] = (x + 1 < 32 && y + 1 < 32) ? (-0.5f * H12) : 0.f;
    co[0] = (x - 1 >= 0 && y - 1 >= 0) ? (-0.5f * H12) : 0.f;
    co[2] = (x + 1 < 32 && y - 1 >= 0) ? ( 0.5f * H12) : 0.f;
    co[6] = (x - 1 >= 0 && y + 1 < 32) ? ( 0.5f * H12) : 0.f;

#pragma unroll
    for (int o = 0; o < 9; ++o)
        g_CO[(op * 9 + o) * NGRID + p] = co[o];
}

// ---------------------------------------------------------------------------
// Kernel 2: precompute band values per row.
//   diag part: tid in [0, 256000)  -> (b,ti,r, 25 offsets)
//   off  part: tid in [256000, 329728) -> (b,i,r, 9 offsets)
// ---------------------------------------------------------------------------
#define DIAG_WORK (NB * NT * NGRID * 25)       // 256000
#define OFF_WORK  (NB * 4 * NGRID * 9)         // 73728

__global__ void precompute_kernel() {
    int tid = blockIdx.x * blockDim.x + threadIdx.x;
    if (tid < DIAG_WORK) {
        int o25 = tid % 25;
        int row = tid / 25;                    // (b*5+ti)*1024 + r
        int r   = row & 1023;
        int bt  = row >> 10;                   // b*5+ti
        int ti  = bt % 5;
        int b   = bt / 5;
        int dy  = o25 / 5 - 2, dx = o25 % 5 - 2;
        int ry = r >> 5, rx = r & 31;
        int cy = ry + dy, cx = rx + dx;
        float val = 0.f;
        if (cy >= 0 && cy < 32 && cx >= 0 && cx < 32) {
            int c = (cy << 5) + cx;
            if (ti == 0) {
                int op = b * 4;
                float acc = 0.f;
#pragma unroll
                for (int dky = -1; dky <= 1; ++dky)
#pragma unroll
                for (int dkx = -1; dkx <= 1; ++dkx) {
                    int ky = ry + dky, kx = rx + dkx;
                    int ody = cy - ky, odx = cx - kx;
                    if (ky >= 0 && ky < 32 && kx >= 0 && kx < 32 &&
                        ody >= -1 && ody <= 1 && odx >= -1 && odx <= 1) {
                        int k = (ky << 5) + kx;
                        float a  = g_CO[(op * 9 + (1 - dky) * 3 + (1 - dkx)) * NGRID + k];
                        float bb = g_CO[(op * 9 + (ody + 1) * 3 + (odx + 1)) * NGRID + k];
                        acc = fmaf(a, bb, acc);
                    }
                }
                val = acc + ((o25 == 12) ? 1.05f : 0.f);
            } else {
                int op = b * 4 + (ti - 1);
                float acc1 = 0.f, acc2 = 0.f;
#pragma unroll
                for (int dky = -1; dky <= 1; ++dky)
#pragma unroll
                for (int dkx = -1; dkx <= 1; ++dkx) {
                    int ky = ry + dky, kx = rx + dkx;
                    int ody = cy - ky, odx = cx - kx;
                    if (ky >= 0 && ky < 32 && kx >= 0 && kx < 32 &&
                        ody >= -1 && ody <= 1 && odx >= -1 && odx <= 1) {
                        int k = (ky << 5) + kx;
                        float dkr = (k == r) ? 1.f : 0.f;
                        float dkc = (k == c) ? 1.f : 0.f;
                        float iM_rk = g_CO[(op * 9 + (dky + 1) * 3 + (dkx + 1)) * NGRID + r] + dkr;
                        float iM_kr = g_CO[(op * 9 + (1 - dky) * 3 + (1 - dkx)) * NGRID + k] + dkr;
                        float iM_kc = g_CO[(op * 9 + (ody + 1) * 3 + (odx + 1)) * NGRID + k] + dkc;
                        float iM_ck = g_CO[(op * 9 + (1 - ody) * 3 + (1 - odx)) * NGRID + c] + dkc;
                        acc1 = fmaf(iM_rk, iM_kc, acc1);
                        acc2 = fmaf(iM_ck, iM_kr, acc2);
                    }
                }
                val = 0.5f * (acc1 + acc2);
                if (o25 == 12) val += (ti == 4) ? 0.05f : 1.05f;
            }
        }
        g_diag[row * 32 + o25] = val;
    } else if (tid < DIAG_WORK + OFF_WORK) {
        int t2  = tid - DIAG_WORK;
        int o9  = t2 % 9;
        int row = t2 / 9;                      // (b*4+i)*1024 + r
        int r   = row & 1023;
        int bi  = row >> 10;                   // b*4+i
        int b   = bi >> 2;
        int i   = bi & 3;
        int dy = o9 / 3 - 1, dx = o9 % 3 - 1;
        int ry = r >> 5, rx = r & 31;
        int cy = ry + dy, cx = rx + dx;
        float val = 0.f;
        if (cy >= 0 && cy < 32 && cx >= 0 && cx < 32) {
            int c  = (cy << 5) + cx;
            int op = b * 4 + i;
            float a  = g_CO[(op * 9 + o9)       * NGRID + r];   // A[r][c]
            float bb = g_CO[(op * 9 + (8 - o9)) * NGRID + c];   // A[c][r]
            float dg = (o9 == 4) ? 2.f : 0.f;
            val = -0.5f * (a + bb + dg);
        }
        g_off[row * 16 + o9] = val;
    }
}

// ---------------------------------------------------------------------------
// Kernel 3: stream out Q. Grid (5, NB*NQ): blockIdx.y = global row,
// blockIdx.x = column time-block (so branch is uniform per block).
// One float4 store per thread, no divisions anywhere.
// ---------------------------------------------------------------------------
__global__ void __launch_bounds__(256) write_q(float4* __restrict__ out) {
    int row = blockIdx.y;                 // 0..10239
    int tj  = blockIdx.x;                 // 0..4
    int b   = row >= NQ;
    int R   = row - (b ? NQ : 0);
    int ti  = R >> 10;
    int r   = R & 1023;

    long gidx = (long)row * 1280 + (tj << 8) + threadIdx.x;

    int d  = ti - tj;
    int ad = d < 0 ? -d : d;

    float4 o4 = make_float4(0.f, 0.f, 0.f, 0.f);

    if (ad <= 1) {
        int c0 = threadIdx.x << 2;        // column within the 1024-wide block
        int ry = r >> 5, rx = r & 31;
        const float* src;
        int halfw, stride;
        if (ad == 0) {
            src = g_diag + (((b * 5 + ti) << 10) + r) * 32;
            halfw = 2; stride = 5;
        } else {
            int i = d > 0 ? tj : ti;      // min(ti, tj)
            src = g_off + (((b * 4 + i) << 10) + r) * 16;
            halfw = 1; stride = 3;
        }
        float v[4];
#pragma unroll
        for (int j = 0; j < 4; ++j) {
            int c  = c0 + j;
            int dy = (c >> 5) - ry;
            int dx = (c & 31) - rx;
            float val = 0.f;
            if (dy >= -halfw && dy <= halfw && dx >= -halfw && dx <= halfw)
                val = src[(dy + halfw) * stride + (dx + halfw)];
            v[j] = val;
        }
        o4 = make_float4(v[0], v[1], v[2], v[3]);
    }
    out[gidx] = o4;
}

extern "C" void kernel_launch(void* const* d_in, const int* in_sizes, int n_in,
                              void* d_out, int out_size) {
    const float* params = (const float*)d_in[0];
    float4* out = (float4*)d_out;

    decode_kernel<<<32, 256>>>(params);

    // 256000 + 73728 = 329728 work items
    precompute_kernel<<<(DIAG_WORK + OFF_WORK + 255) / 256, 256>>>();

    dim3 grid(5, NB * NQ);   // (col time-block, global row)
    write_q<<<grid, 256>>>(out);
}

// round 3
// speedup vs baseline: 2.0307x; 1.0183x over previous
#include <cuda_runtime.h>

// Problem constants
#define NB    2
#define NT    5
#define NGRID 1024            // 32*32 spatial points
#define NQ    5120            // NT * NGRID

// Diagonal-block band values: [b*5+ti][row][25 offsets, padded to 32]
__device__ float g_diag[NB * NT * NGRID * 32];
// Off-diagonal-block band values: [b*4+i][row][9 offsets, padded to 16]
__device__ float g_off[NB * 4 * NGRID * 16];

__device__ __forceinline__ float sp10(float x) {
    float z = 10.f * x;
    return (fmaxf(z, 0.f) + log1pf(expf(-fabsf(z)))) * 0.1f;
}

// Decode the 9 stencil coefficients of operator (b, i) at point p.
// i in 0..3 corresponds to time slice t = i+1.
__device__ __forceinline__ void decode_point(const float* __restrict__ params,
                                             int b, int i, int p, float co[9]) {
    int t = i + 1;
    // kappa / m use the "raw reshape" mixing: flat = p*5 + t over a (5,32,32) block
    int flat = p * 5 + t;
    int tor  = flat >> 10;
    int rem  = flat & 1023;

    const float* Pb = params + b * 35 * NGRID;
    float kap = sp10(Pb[(0  + tor) * NGRID + rem]);
    float m1  =      Pb[(5  + tor) * NGRID + rem];
    float m2  =      Pb[(10 + tor) * NGRID + rem];

    float gam = sp10(Pb[(15 + t) * NGRID + p]);
    float vx  =      Pb[(20 + t) * NGRID + p];
    float vy  =      Pb[(25 + t) * NGRID + p];

    float H11 = gam + vx * vx;
    float H22 = gam + vy * vy;
    float H12 = vx * vy;

    int y = p >> 5, x = p & 31;

    co[4] = kap * kap + 2.f * H11 + 2.f * H22;
    co[5] = (x + 1 < 32)            ? (-H11 + 0.5f * m1) : 0.f;
    co[3] = (x - 1 >= 0)            ? (-H11 - 0.5f * m1) : 0.f;
    co[7] = (y + 1 < 32)            ? (-H22 + 0.5f * m2) : 0.f;
    co[1] = (y - 1 >= 0)            ? (-H22 - 0.5f * m2) : 0.f;
    co[8] = (x + 1 < 32 && y + 1 < 32) ? (-0.5f * H12) : 0.f;
    co[0] = (x - 1 >= 0 && y - 1 >= 0) ? (-0.5f * H12) : 0.f;
    co[2] = (x + 1 < 32 && y - 1 >= 0) ? ( 0.5f * H12) : 0.f;
    co[6] = (x - 1 >= 0 && y + 1 < 32) ? ( 0.5f * H12) : 0.f;
}

// ---------------------------------------------------------------------------
// Fused kernel: decode the needed operator table into smem, then compute band
// values. Grid layout (112 blocks of 256):
//   blocks [0,80):   diag. bx = bt*8 + sub; bt = b*5+ti; rows [sub*128, +128)
//   blocks [80,112): off.  idx = bx-80 = bi*4 + sub;     rows [sub*256, +256)
// ---------------------------------------------------------------------------
__global__ void __launch_bounds__(256) precompute_kernel(const float* __restrict__ params) {
    __shared__ float sco[9 * NGRID];   // 36 KB: sco[o*1024 + p]

    int bx  = blockIdx.x;
    int tid = threadIdx.x;

    bool is_diag = bx < 80;
    int b, i, ti = 0, sub;
    if (is_diag) {
        sub = bx & 7;
        int bt = bx >> 3;          // 0..9
        ti = bt % 5;
        b  = bt / 5;
        i  = (ti == 0) ? 0 : ti - 1;
    } else {
        int idx = bx - 80;
        sub = idx & 3;
        int bi = idx >> 2;         // 0..7
        b = bi >> 2;
        i = bi & 3;
    }

    // Cooperative decode of full coefficient table for this operator.
#pragma unroll
    for (int q = 0; q < 4; ++q) {
        int p = tid + (q << 8);
        float co[9];
        decode_point(params, b, i, p, co);
#pragma unroll
        for (int o = 0; o < 9; ++o)
            sco[o * NGRID + p] = co[o];
    }
    __syncthreads();

    if (is_diag) {
        int r0 = sub << 7;                       // 128 rows per block
        int rowbase = ((b * 5 + ti) << 10);
        for (int it = tid; it < 128 * 25; it += 256) {
            int lr  = it / 25;
            int o25 = it - lr * 25;
            int r   = r0 + lr;
            int dy  = o25 / 5 - 2, dx = o25 % 5 - 2;
            int ry = r >> 5, rx = r & 31;
            int cy = ry + dy, cx = rx + dx;
            float val = 0.f;
            if (cy >= 0 && cy < 32 && cx >= 0 && cx < 32) {
                int c = (cy << 5) + cx;
                if (ti == 0) {
                    float acc = 0.f;
#pragma unroll
                    for (int dky = -1; dky <= 1; ++dky)
#pragma unroll
                    for (int dkx = -1; dkx <= 1; ++dkx) {
                        int ky = ry + dky, kx = rx + dkx;
                        int ody = cy - ky, odx = cx - kx;
                        if (ky >= 0 && ky < 32 && kx >= 0 && kx < 32 &&
                            ody >= -1 && ody <= 1 && odx >= -1 && odx <= 1) {
                            int k = (ky << 5) + kx;
                            float a  = sco[((1 - dky) * 3 + (1 - dkx)) * NGRID + k];
                            float bb = sco[((ody + 1) * 3 + (odx + 1)) * NGRID + k];
                            acc = fmaf(a, bb, acc);
                        }
                    }
                    val = acc + ((o25 == 12) ? 1.05f : 0.f);
                } else {
                    float acc1 = 0.f, acc2 = 0.f;
#pragma unroll
                    for (int dky = -1; dky <= 1; ++dky)
#pragma unroll
                    for (int dkx = -1; dkx <= 1; ++dkx) {
                        int ky = ry + dky, kx = rx + dkx;
                        int ody = cy - ky, odx = cx - kx;
                        if (ky >= 0 && ky < 32 && kx >= 0 && kx < 32 &&
                            ody >= -1 && ody <= 1 && odx >= -1 && odx <= 1) {
                            int k = (ky << 5) + kx;
                            float dkr = (k == r) ? 1.f : 0.f;
                            float dkc = (k == c) ? 1.f : 0.f;
                            float iM_rk = sco[((dky + 1) * 3 + (dkx + 1)) * NGRID + r] + dkr;
                            float iM_kr = sco[((1 - dky) * 3 + (1 - dkx)) * NGRID + k] + dkr;
                            float iM_kc = sco[((ody + 1) * 3 + (odx + 1)) * NGRID + k] + dkc;
                            float iM_ck = sco[((1 - ody) * 3 + (1 - odx)) * NGRID + c] + dkc;
                            acc1 = fmaf(iM_rk, iM_kc, acc1);
                            acc2 = fmaf(iM_ck, iM_kr, acc2);
                        }
                    }
                    val = 0.5f * (acc1 + acc2);
                    if (o25 == 12) val += (ti == 4) ? 0.05f : 1.05f;
                }
            }
            g_diag[(rowbase + r) * 32 + o25] = val;
        }
    } else {
        int r0 = sub << 8;                       // 256 rows per block
        int rowbase = ((b * 4 + i) << 10);
        for (int it = tid; it < 256 * 9; it += 256) {
            int lr = it / 9;
            int o9 = it - lr * 9;
            int r  = r0 + lr;
            int dy = o9 / 3 - 1, dx = o9 % 3 - 1;
            int ry = r >> 5, rx = r & 31;
            int cy = ry + dy, cx = rx + dx;
            float val = 0.f;
            if (cy >= 0 && cy < 32 && cx >= 0 && cx < 32) {
                int c  = (cy << 5) + cx;
                float a  = sco[o9       * NGRID + r];   // A[r][c]
                float bb = sco[(8 - o9) * NGRID + c];   // A[c][r]
                float dg = (o9 == 4) ? 2.f : 0.f;
                val = -0.5f * (a + bb + dg);
            }
            g_off[(rowbase + r) * 16 + o9] = val;
        }
    }
}

// ---------------------------------------------------------------------------
// Kernel 2: stream out Q. One block per global row; each thread owns 4 columns
// and writes all 5 column time-blocks (5 float4 streaming stores).
// ---------------------------------------------------------------------------
__global__ void __launch_bounds__(256) write_q(float4* __restrict__ out) {
    int row = blockIdx.x;                 // 0..10239
    int b   = row >= NQ;
    int R   = row - (b ? NQ : 0);
    int ti  = R >> 10;
    int r   = R & 1023;

    int tid = threadIdx.x;
    int c0  = tid << 2;
    int ry  = r >> 5, rx = r & 31;

    const float* dsrc  = g_diag + ((((b * 5 + ti) << 10) + r) << 5);
    const float* losrc = g_off  + ((((b * 4 + (ti - 1)) << 10) + r) << 4);
    const float* hisrc = g_off  + ((((b * 4 + ti) << 10) + r) << 4);
    bool has_lo = (ti > 0), has_hi = (ti < 4);

    float vd[4], vlo[4], vhi[4];
#pragma unroll
    for (int j = 0; j < 4; ++j) {
        int c  = c0 + j;
        int dy = (c >> 5) - ry;
        int dx = (c & 31) - rx;
        bool in2 = (dy >= -2 && dy <= 2 && dx >= -2 && dx <= 2);
        bool in1 = (dy >= -1 && dy <= 1 && dx >= -1 && dx <= 1);
        vd[j]  = in2              ? dsrc [(dy + 2) * 5 + (dx + 2)] : 0.f;
        vlo[j] = (in1 && has_lo) ? losrc[(dy + 1) * 3 + (dx + 1)] : 0.f;
        vhi[j] = (in1 && has_hi) ? hisrc[(dy + 1) * 3 + (dx + 1)] : 0.f;
    }
    float4 z   = make_float4(0.f, 0.f, 0.f, 0.f);
    float4 d4  = make_float4(vd[0],  vd[1],  vd[2],  vd[3]);
    float4 lo4 = make_float4(vlo[0], vlo[1], vlo[2], vlo[3]);
    float4 hi4 = make_float4(vhi[0], vhi[1], vhi[2], vhi[3]);

    float4* base = out + (long)row * 1280 + tid;
#pragma unroll
    for (int tj = 0; tj < 5; ++tj) {
        float4 v = z;
        if (tj == ti)          v = d4;
        else if (tj == ti - 1) v = lo4;
        else if (tj == ti + 1) v = hi4;
        __stcs(&base[tj * 256], v);
    }
}

extern "C" void kernel_launch(void* const* d_in, const int* in_sizes, int n_in,
                              void* d_out, int out_size) {
    const float* params = (const float*)d_in[0];
    float4* out = (float4*)d_out;

    precompute_kernel<<<112, 256>>>(params);
    write_q<<<NB * NQ, 256>>>(out);
}

// round 4
// speedup vs baseline: 2.0427x; 1.0059x over previous
#include <cuda_runtime.h>

// Problem constants
#define NB    2
#define NT    5
#define NGRID 1024            // 32*32 spatial points
#define NQ    5120            // NT * NGRID

// Diagonal-block band values: [b*5+ti][row][25 offsets, padded to 32]
__device__ float g_diag[NB * NT * NGRID * 32];
// Off-diagonal-block band values: [b*4+i][row][9 offsets, padded to 16]
__device__ float g_off[NB * 4 * NGRID * 16];

__device__ __forceinline__ float sp10(float x) {
    float z = 10.f * x;
    return (fmaxf(z, 0.f) + log1pf(expf(-fabsf(z)))) * 0.1f;
}

// Decode the 9 stencil coefficients of operator (b, i) at point p.
__device__ __forceinline__ void decode_point(const float* __restrict__ params,
                                             int b, int i, int p, float co[9]) {
    int t = i + 1;
    // kappa / m use the "raw reshape" mixing: flat = p*5 + t over a (5,32,32) block
    int flat = p * 5 + t;
    int tor  = flat >> 10;
    int rem  = flat & 1023;

    const float* Pb = params + b * 35 * NGRID;
    float kap = sp10(Pb[(0  + tor) * NGRID + rem]);
    float m1  =      Pb[(5  + tor) * NGRID + rem];
    float m2  =      Pb[(10 + tor) * NGRID + rem];

    float gam = sp10(Pb[(15 + t) * NGRID + p]);
    float vx  =      Pb[(20 + t) * NGRID + p];
    float vy  =      Pb[(25 + t) * NGRID + p];

    float H11 = gam + vx * vx;
    float H22 = gam + vy * vy;
    float H12 = vx * vy;

    int y = p >> 5, x = p & 31;

    co[4] = kap * kap + 2.f * H11 + 2.f * H22;
    co[5] = (x + 1 < 32)            ? (-H11 + 0.5f * m1) : 0.f;
    co[3] = (x - 1 >= 0)            ? (-H11 - 0.5f * m1) : 0.f;
    co[7] = (y + 1 < 32)            ? (-H22 + 0.5f * m2) : 0.f;
    co[1] = (y - 1 >= 0)            ? (-H22 - 0.5f * m2) : 0.f;
    co[8] = (x + 1 < 32 && y + 1 < 32) ? (-0.5f * H12) : 0.f;
    co[0] = (x - 1 >= 0 && y - 1 >= 0) ? (-0.5f * H12) : 0.f;
    co[2] = (x + 1 < 32 && y - 1 >= 0) ? ( 0.5f * H12) : 0.f;
    co[6] = (x - 1 >= 0 && y + 1 < 32) ? ( 0.5f * H12) : 0.f;
}

// ---------------------------------------------------------------------------
// Fused decode+band kernel with HALO-ONLY decode.
//   blocks [0,80):   diag. bx = bt*8 + sub; bt = b*5+ti; rows [sub*128, +128)
//                    decode y in [4*sub-2, 4*sub+6)   (8 y-rows, 256 pts)
//   blocks [80,112): off.  idx = bx-80 = bi*4 + sub;   rows [sub*256, +256)
//                    decode y in [8*sub-1, 8*sub+9)   (10 y-rows, 320 pts)
// smem sco[o][lp] with lp = p - base_y*32.
// ---------------------------------------------------------------------------
#define SPAN_MAX 320

__global__ void __launch_bounds__(256) precompute_kernel(const float* __restrict__ params) {
    __shared__ float sco[9 * SPAN_MAX];   // 11.25 KB

    int bx  = blockIdx.x;
    int tid = threadIdx.x;

    bool is_diag = bx < 80;
    int b, i, ti = 0, sub, base_y, span;
    if (is_diag) {
        sub = bx & 7;
        int bt = bx >> 3;          // 0..9
        ti = bt % 5;
        b  = bt / 5;
        i  = (ti == 0) ? 0 : ti - 1;
        base_y = 4 * sub - 2; span = 8;
    } else {
        int idx = bx - 80;
        sub = idx & 3;
        int bi = idx >> 2;         // 0..7
        b = bi >> 2;
        i = bi & 3;
        base_y = 8 * sub - 1; span = 10;
    }

    int npts  = span << 5;
    int pbase = base_y << 5;       // lp = p - pbase
    for (int lp = tid; lp < npts; lp += 256) {
        int y = base_y + (lp >> 5);
        if (y >= 0 && y < 32) {
            float co[9];
            decode_point(params, b, i, (y << 5) + (lp & 31), co);
#pragma unroll
            for (int o = 0; o < 9; ++o)
                sco[o * SPAN_MAX + lp] = co[o];
        }
    }
    __syncthreads();

    if (is_diag) {
        int r0 = sub << 7;                       // 128 rows per block
        int rowbase = ((b * 5 + ti) << 10);
        for (int it = tid; it < 128 * 25; it += 256) {
            int lr  = it / 25;
            int o25 = it - lr * 25;
            int r   = r0 + lr;
            int dy  = o25 / 5 - 2, dx = o25 % 5 - 2;
            int ry = r >> 5, rx = r & 31;
            int cy = ry + dy, cx = rx + dx;
            float val = 0.f;
            if (cy >= 0 && cy < 32 && cx >= 0 && cx < 32) {
                int c = (cy << 5) + cx;
                int lc = c - pbase;
                int lrr = r - pbase;
                if (ti == 0) {
                    float acc = 0.f;
#pragma unroll
                    for (int dky = -1; dky <= 1; ++dky)
#pragma unroll
                    for (int dkx = -1; dkx <= 1; ++dkx) {
                        int ky = ry + dky, kx = rx + dkx;
                        int ody = cy - ky, odx = cx - kx;
                        if (ky >= 0 && ky < 32 && kx >= 0 && kx < 32 &&
                            ody >= -1 && ody <= 1 && odx >= -1 && odx <= 1) {
                            int lk = ((ky << 5) + kx) - pbase;
                            float a  = sco[((1 - dky) * 3 + (1 - dkx)) * SPAN_MAX + lk];
                            float bb = sco[((ody + 1) * 3 + (odx + 1)) * SPAN_MAX + lk];
                            acc = fmaf(a, bb, acc);
                        }
                    }
                    val = acc + ((o25 == 12) ? 1.05f : 0.f);
                } else {
                    float acc1 = 0.f, acc2 = 0.f;
#pragma unroll
                    for (int dky = -1; dky <= 1; ++dky)
#pragma unroll
                    for (int dkx = -1; dkx <= 1; ++dkx) {
                        int ky = ry + dky, kx = rx + dkx;
                        int ody = cy - ky, odx = cx - kx;
                        if (ky >= 0 && ky < 32 && kx >= 0 && kx < 32 &&
                            ody >= -1 && ody <= 1 && odx >= -1 && odx <= 1) {
                            int k  = (ky << 5) + kx;
                            int lk = k - pbase;
                            float dkr = (k == r) ? 1.f : 0.f;
                            float dkc = (k == c) ? 1.f : 0.f;
                            float iM_rk = sco[((dky + 1) * 3 + (dkx + 1)) * SPAN_MAX + lrr] + dkr;
                            float iM_kr = sco[((1 - dky) * 3 + (1 - dkx)) * SPAN_MAX + lk] + dkr;
                            float iM_kc = sco[((ody + 1) * 3 + (odx + 1)) * SPAN_MAX + lk] + dkc;
                            float iM_ck = sco[((1 - ody) * 3 + (1 - odx)) * SPAN_MAX + lc] + dkc;
                            acc1 = fmaf(iM_rk, iM_kc, acc1);
                            acc2 = fmaf(iM_ck, iM_kr, acc2);
                        }
                    }
                    val = 0.5f * (acc1 + acc2);
                    if (o25 == 12) val += (ti == 4) ? 0.05f : 1.05f;
                }
            }
            g_diag[(rowbase + r) * 32 + o25] = val;
        }
    } else {
        int r0 = sub << 8;                       // 256 rows per block
        int rowbase = ((b * 4 + i) << 10);
        for (int it = tid; it < 256 * 9; it += 256) {
            int lr = it / 9;
            int o9 = it - lr * 9;
            int r  = r0 + lr;
            int dy = o9 / 3 - 1, dx = o9 % 3 - 1;
            int ry = r >> 5, rx = r & 31;
            int cy = ry + dy, cx = rx + dx;
            float val = 0.f;
            if (cy >= 0 && cy < 32 && cx >= 0 && cx < 32) {
                int lc = ((cy << 5) + cx) - pbase;
                int lrr = r - pbase;
                float a  = sco[o9       * SPAN_MAX + lrr];   // A[r][c]
                float bb = sco[(8 - o9) * SPAN_MAX + lc];    // A[c][r]
                float dg = (o9 == 4) ? 2.f : 0.f;
                val = -0.5f * (a + bb + dg);
            }
            g_off[(rowbase + r) * 16 + o9] = val;
        }
    }
}

// ---------------------------------------------------------------------------
// Kernel 2: stream out Q. One block per global row. Since each thread's 4
// columns share one y-row, dy is scalar per thread -> cheap uniform fast path
// for out-of-band threads (just 5 zero float4 streaming stores).
// ---------------------------------------------------------------------------
__global__ void __launch_bounds__(256) write_q(float4* __restrict__ out) {
    int row = blockIdx.x;                 // 0..10239
    int b   = row >= NQ;
    int R   = row - (b ? NQ : 0);
    int ti  = R >> 10;
    int r   = R & 1023;

    int tid = threadIdx.x;
    int c0  = tid << 2;
    int ry  = r >> 5, rx = r & 31;
    int dy  = (c0 >> 5) - ry;             // uniform over the thread's 4 columns

    float4 z  = make_float4(0.f, 0.f, 0.f, 0.f);
    float4 d4 = z, lo4 = z, hi4 = z;

    if (dy >= -2 && dy <= 2) {
        int dxb = (c0 & 31) - rx;         // dx for j=0; j adds 0..3
        const float* drow = g_diag + ((((b * 5 + ti) << 10) + r) << 5)
                          + (dy + 2) * 5 + 2;
        float vd[4];
#pragma unroll
        for (int j = 0; j < 4; ++j) {
            int dx = dxb + j;
            vd[j] = (dx >= -2 && dx <= 2) ? drow[dx] : 0.f;
        }
        d4 = make_float4(vd[0], vd[1], vd[2], vd[3]);

        if (dy >= -1 && dy <= 1) {
            bool has_lo = (ti > 0), has_hi = (ti < 4);
            const float* lorow = g_off + ((((b * 4 + (ti - 1)) << 10) + r) << 4)
                               + (dy + 1) * 3 + 1;
            const float* hirow = g_off + ((((b * 4 + ti) << 10) + r) << 4)
                               + (dy + 1) * 3 + 1;
            float vl[4], vh[4];
#pragma unroll
            for (int j = 0; j < 4; ++j) {
                int dx = dxb + j;
                bool in1 = (dx >= -1 && dx <= 1);
                vl[j] = (in1 && has_lo) ? lorow[dx] : 0.f;
                vh[j] = (in1 && has_hi) ? hirow[dx] : 0.f;
            }
            lo4 = make_float4(vl[0], vl[1], vl[2], vl[3]);
            hi4 = make_float4(vh[0], vh[1], vh[2], vh[3]);
        }
    }

    float4* base = out + (long)row * 1280 + tid;
#pragma unroll
    for (int tj = 0; tj < 5; ++tj) {
        float4 v = z;
        if (tj == ti)          v = d4;
        else if (tj == ti - 1) v = lo4;
        else if (tj == ti + 1) v = hi4;
        __stcs(&base[tj * 256], v);
    }
}

extern "C" void kernel_launch(void* const* d_in, const int* in_sizes, int n_in,
                              void* d_out, int out_size) {
    const float* params = (const float*)d_in[0];
    float4* out = (float4*)d_out;

    precompute_kernel<<<112, 256>>>(params);
    write_q<<<NB * NQ, 256>>>(out);
}